// round 7
// baseline (speedup 1.0000x reference)
#include <cuda_runtime.h>
#include <cuda_bf16.h>
#include <cstdint>

// Problem constants (fixed by the dataset)
#define BQ    1200      // B*Q rows
#define NC    80        // classes
#define NT    200       // targets
#define HW    65536     // H*W
#define NP    12544     // sampled points (K of the GEMM)
#define NW    2048      // HW/32 mask words

// GEMM tiling
#define BM    32
#define BN    64
#define BK    64
#define KPAD  72        // smem row stride in bf16 (+8 avoids bank conflicts)
#define KIT   (NP / BK) // 196
#define KSPLIT 4
#define ITERS (KIT / KSPLIT)  // 49

#define AB_STAGE (BM * KPAD)          // 2304 elems per X/S stage
#define T_STAGE  (BN * KPAD)          // 4608 elems per T stage
#define SMEM_ELEMS (3 * (2 * AB_STAGE + T_STAGE))
#define SMEM_BYTES (SMEM_ELEMS * 2)   // 55296 bytes

// ---------------- scratch (static device allocations; no cudaMalloc) -------
__device__ __align__(256) __nv_bfloat16 g_X[(size_t)BQ * NP];   // x (bf16)
__device__ __align__(256) __nv_bfloat16 g_S[(size_t)BQ * NP];   // sigmoid(x)
__device__ __align__(256) __nv_bfloat16 g_T[(size_t)NT * NP];   // gathered targets
__device__ float g_CC[BQ * NT];    // class cost  (-prob[tgt_id])
__device__ float g_sumSP[BQ];      // sum softplus(x)  per row
__device__ float g_sumS[BQ];       // sum sigmoid(x)   per row
__device__ float g_sumT[NT];       // sum t            per target
__device__ unsigned g_maskw[NW];   // selection bitmask, one bit per element
__device__ int      g_pref[NW];    // exclusive prefix of popcounts
__device__ float g_PX[(size_t)KSPLIT * BQ * NT];  // split-K partials of x@t'
__device__ float g_PS[(size_t)KSPLIT * BQ * NT];  // split-K partials of s@t'

// ---------------- helpers ---------------------------------------------------
__device__ __forceinline__ void cp16(void* smem, const void* gmem) {
    unsigned s = (unsigned)__cvta_generic_to_shared(smem);
    asm volatile("cp.async.cg.shared.global [%0], [%1], 16;\n" :: "r"(s), "l"(gmem));
}
__device__ __forceinline__ void cp_commit() {
    asm volatile("cp.async.commit_group;\n" ::: "memory");
}
__device__ __forceinline__ void cp_wait1() {
    asm volatile("cp.async.wait_group 1;\n" ::: "memory");
}
__device__ __forceinline__ void ldsm4(unsigned addr, unsigned& r0, unsigned& r1,
                                      unsigned& r2, unsigned& r3) {
    asm volatile("ldmatrix.sync.aligned.m8n8.x4.shared.b16 {%0,%1,%2,%3}, [%4];\n"
                 : "=r"(r0), "=r"(r1), "=r"(r2), "=r"(r3) : "r"(addr));
}
__device__ __forceinline__ void mma16816(float* d, const unsigned* a,
                                         unsigned b0, unsigned b1) {
    asm volatile(
        "mma.sync.aligned.m16n8k16.row.col.f32.bf16.bf16.f32 "
        "{%0,%1,%2,%3},{%4,%5,%6,%7},{%8,%9},{%0,%1,%2,%3};\n"
        : "+f"(d[0]), "+f"(d[1]), "+f"(d[2]), "+f"(d[3])
        : "r"(a[0]), "r"(a[1]), "r"(a[2]), "r"(a[3]), "r"(b0), "r"(b1));
}

__device__ __forceinline__ float block_reduce_sum(float v, float* sbuf) {
    #pragma unroll
    for (int o = 16; o > 0; o >>= 1) v += __shfl_xor_sync(0xFFFFFFFFu, v, o);
    int w = threadIdx.x >> 5;
    if ((threadIdx.x & 31) == 0) sbuf[w] = v;
    __syncthreads();
    float r = 0.f;
    if (threadIdx.x < 8) {
        r = sbuf[threadIdx.x];
        #pragma unroll
        for (int o = 4; o > 0; o >>= 1) r += __shfl_xor_sync(0xFFu, r, o);
    }
    return r;  // valid in thread 0
}

// ---------------- kernel 0: build selection mask + prefix -------------------
// 1 block x 1024 threads. Indices are 12544 distinct values in [0, 65536).
__global__ void sort_kernel(const int* __restrict__ point_idx) {
    __shared__ unsigned mask[NW];     // 65536 bits
    __shared__ int psum[1024];
    int tid = threadIdx.x;
    mask[tid] = 0u; mask[tid + 1024] = 0u;
    __syncthreads();
    for (int p = tid; p < NP; p += 1024) {
        int v = point_idx[p];
        atomicOr(&mask[v >> 5], 1u << (v & 31));
    }
    __syncthreads();
    unsigned m0 = mask[2 * tid], m1 = mask[2 * tid + 1];
    int c0 = __popc(m0);
    int s = c0 + __popc(m1);
    psum[tid] = s;
    __syncthreads();
    // Hillis-Steele inclusive scan over 1024 entries
    #pragma unroll
    for (int off = 1; off < 1024; off <<= 1) {
        int v = (tid >= off) ? psum[tid - off] : 0;
        __syncthreads();
        psum[tid] += v;
        __syncthreads();
    }
    int excl = psum[tid] - s;   // exclusive prefix
    g_maskw[2 * tid]     = m0;
    g_maskw[2 * tid + 1] = m1;
    g_pref[2 * tid]      = excl;
    g_pref[2 * tid + 1]  = excl + c0;
}

// ---------------- kernel 1: class cost --------------------------------------
__global__ void class_kernel(const float* __restrict__ logits,
                             const int* __restrict__ tgt_ids) {
    __shared__ float probs[4][NC];
    __shared__ int s_ids[NT];
    int warp = threadIdx.x >> 5, lane = threadIdx.x & 31;
    for (int i = threadIdx.x; i < NT; i += 128) s_ids[i] = tgt_ids[i];
    __syncthreads();

    int r = blockIdx.x * 4 + warp;
    const float* L = logits + (size_t)r * NC;
    float v[3];
    float mx = -1e30f;
    #pragma unroll
    for (int j = 0; j < 3; j++) {
        int c = lane + 32 * j;
        v[j] = (c < NC) ? L[c] : -1e30f;
        mx = fmaxf(mx, v[j]);
    }
    #pragma unroll
    for (int o = 16; o > 0; o >>= 1) mx = fmaxf(mx, __shfl_xor_sync(~0u, mx, o));
    float e[3], se = 0.f;
    #pragma unroll
    for (int j = 0; j < 3; j++) {
        int c = lane + 32 * j;
        e[j] = (c < NC) ? expf(v[j] - mx) : 0.f;
        se += e[j];
    }
    #pragma unroll
    for (int o = 16; o > 0; o >>= 1) se += __shfl_xor_sync(~0u, se, o);
    float inv = 1.f / se;
    #pragma unroll
    for (int j = 0; j < 3; j++) {
        int c = lane + 32 * j;
        if (c < NC) probs[warp][c] = e[j] * inv;
    }
    __syncwarp();
    for (int n = lane; n < NT; n += 32)
        g_CC[r * NT + n] = -probs[warp][s_ids[n]];
}

// ---------------- kernel 2: stream + compact targets -------------------------
// grid NT x 256 threads; fully coalesced full-row read, compact via mask
__global__ void gather_t_kernel(const float* __restrict__ tgt_masks) {
    __shared__ float sbuf[8];
    int n = blockIdx.x;
    const float4* row = (const float4*)(tgt_masks + (size_t)n * HW);
    __nv_bfloat16* dst = g_T + (size_t)n * NP;
    float st = 0.f;
    int tid = threadIdx.x;
    #pragma unroll 1
    for (int it = 0; it < 8; ++it) {
        int w = tid + it * 256;             // word index 0..2047
        unsigned m = g_maskw[w];
        int p = g_pref[w];
        const float4* src = row + w * 8;    // 32 floats = 8 float4
        #pragma unroll
        for (int j = 0; j < 8; ++j) {
            float4 f = __ldg(src + j);
            unsigned nib = (m >> (4 * j)) & 0xFu;
            if (nib & 1u) { dst[p++] = __float2bfloat16(f.x); st += f.x; }
            if (nib & 2u) { dst[p++] = __float2bfloat16(f.y); st += f.y; }
            if (nib & 4u) { dst[p++] = __float2bfloat16(f.z); st += f.z; }
            if (nib & 8u) { dst[p++] = __float2bfloat16(f.w); st += f.w; }
        }
    }
    float tot = block_reduce_sum(st, sbuf);
    if (threadIdx.x == 0) g_sumT[n] = tot;
}

// ---------------- kernel 3: stream + compact + transform predictions ---------
// grid BQ x 256 threads
__global__ void gather_x_kernel(const float* __restrict__ pred_masks) {
    __shared__ float sbuf[8];
    int mrow = blockIdx.x;
    const float4* row = (const float4*)(pred_masks + (size_t)mrow * HW);
    __nv_bfloat16* dX = g_X + (size_t)mrow * NP;
    __nv_bfloat16* dS = g_S + (size_t)mrow * NP;
    float sSP = 0.f, sS = 0.f;
    int tid = threadIdx.x;
    #pragma unroll 1
    for (int it = 0; it < 8; ++it) {
        int w = tid + it * 256;
        unsigned m = g_maskw[w];
        int p = g_pref[w];
        const float4* src = row + w * 8;
        #pragma unroll
        for (int j = 0; j < 8; ++j) {
            float4 f = __ldg(src + j);
            unsigned nib = (m >> (4 * j)) & 0xFu;
            float xv;
            #pragma unroll
            for (int c = 0; c < 4; ++c) {
                if (nib & (1u << c)) {
                    xv = (c == 0) ? f.x : (c == 1) ? f.y : (c == 2) ? f.z : f.w;
                    float sp = fmaxf(xv, 0.f) + log1pf(expf(-fabsf(xv)));
                    float sg = 1.f / (1.f + expf(-xv));
                    dX[p] = __float2bfloat16(xv);
                    dS[p] = __float2bfloat16(sg);
                    ++p;
                    sSP += sp; sS += sg;
                }
            }
        }
    }
    float t1 = block_reduce_sum(sSP, sbuf);
    if (threadIdx.x == 0) g_sumSP[mrow] = t1;
    __syncthreads();
    float t2 = block_reduce_sum(sS, sbuf);
    if (threadIdx.x == 0) g_sumS[mrow] = t2;
}

// ---------------- kernel 4: dual GEMM, split-K, 3-stage pipeline -------------
// grid (4, 38, KSPLIT) x 256 threads (8 warps: 2(M) x 4(N))
__global__ void __launch_bounds__(256)
gemm_kernel() {
    extern __shared__ __nv_bfloat16 smem[];
    __nv_bfloat16* sX = smem;                    // [3][BM][KPAD]
    __nv_bfloat16* sS = smem + 3 * AB_STAGE;     // [3][BM][KPAD]
    __nv_bfloat16* sT = smem + 6 * AB_STAGE;     // [3][BN][KPAD]

    const int tid  = threadIdx.x;
    const int m0   = blockIdx.y * BM;
    const int n0   = blockIdx.x * BN;
    const int kbase = blockIdx.z * ITERS * BK;

    // producer mapping
    const int pr  = tid >> 3;             // 0..31
    const int pc  = (tid & 7) * 8;        // element col of the 16B vector
    const size_t gxm = (size_t)min(m0 + pr, BQ - 1) * NP;
    const size_t gt0 = (size_t)min(n0 + pr, NT - 1) * NP;
    const size_t gt1 = (size_t)min(n0 + pr + 32, NT - 1) * NP;

    // consumer mapping
    const int warp = tid >> 5, lane = tid & 31;
    const int wm = (warp >> 2) * 16;      // 0 or 16
    const int wn = (warp & 3) * 16;       // 0,16,32,48
    const int lrow = lane & 15;
    const int lcol = (lane >> 4) * 8;

    const unsigned baseX = (unsigned)__cvta_generic_to_shared(sX);
    const unsigned baseS = (unsigned)__cvta_generic_to_shared(sS);
    const unsigned baseT = (unsigned)__cvta_generic_to_shared(sT);
    const unsigned offA  = (unsigned)(((wm + lrow) * KPAD + lcol) * 2);
    const unsigned offB  = (unsigned)(((wn + lrow) * KPAD + lcol) * 2);
    const unsigned stgAB = (unsigned)(AB_STAGE * 2);
    const unsigned stgT  = (unsigned)(T_STAGE * 2);

    float accX[2][4] = {}, accS[2][4] = {};

    auto issue = [&](int st, int buf) {
        const int k0 = kbase + st * BK;
        cp16(sX + buf * AB_STAGE + pr * KPAD + pc,        g_X + gxm + k0 + pc);
        cp16(sS + buf * AB_STAGE + pr * KPAD + pc,        g_S + gxm + k0 + pc);
        cp16(sT + buf * T_STAGE + pr * KPAD + pc,         g_T + gt0 + k0 + pc);
        cp16(sT + buf * T_STAGE + (pr + 32) * KPAD + pc,  g_T + gt1 + k0 + pc);
    };

    // prologue: stages 0,1
    issue(0, 0); cp_commit();
    issue(1, 1); cp_commit();

    #pragma unroll 1
    for (int it = 0; it < ITERS; ++it) {
        cp_wait1();
        __syncthreads();

        const int buf = it % 3;
        const unsigned aX = baseX + buf * stgAB + offA;
        const unsigned aS = baseS + buf * stgAB + offA;
        const unsigned aT = baseT + buf * stgT  + offB;
        #pragma unroll
        for (int kk = 0; kk < 4; ++kk) {
            unsigned xf[4], sf[4], tf[4];
            ldsm4(aX + kk * 32, xf[0], xf[1], xf[2], xf[3]);
            ldsm4(aS + kk * 32, sf[0], sf[1], sf[2], sf[3]);
            ldsm4(aT + kk * 32, tf[0], tf[1], tf[2], tf[3]);
            mma16816(accX[0], xf, tf[0], tf[2]);
            mma16816(accX[1], xf, tf[1], tf[3]);
            mma16816(accS[0], sf, tf[0], tf[2]);
            mma16816(accS[1], sf, tf[1], tf[3]);
        }

        // prefetch stage it+2 into the buffer consumed at iter it-1.
        const int st = it + 2;
        if (st < ITERS) issue(st, st % 3);
        cp_commit();   // always commit to keep group count aligned
    }

    // write split-K partials
    const int groupId = lane >> 2, tig = lane & 3;
    float* px = g_PX + (size_t)blockIdx.z * BQ * NT;
    float* ps = g_PS + (size_t)blockIdx.z * BQ * NT;
    #pragma unroll
    for (int nsub = 0; nsub < 2; ++nsub) {
        #pragma unroll
        for (int e2 = 0; e2 < 4; ++e2) {
            int mm = m0 + wm + groupId + ((e2 >= 2) ? 8 : 0);
            int nn = n0 + wn + nsub * 8 + 2 * tig + (e2 & 1);
            if (mm < BQ && nn < NT) {
                px[mm * NT + nn] = accX[nsub][e2];
                ps[mm * NT + nn] = accS[nsub][e2];
            }
        }
    }
}

// ---------------- kernel 5: combine partials + epilogue ----------------------
__global__ void combine_kernel(float* __restrict__ out) {
    int idx = blockIdx.x * 256 + threadIdx.x;
    if (idx >= BQ * NT) return;
    int mm = idx / NT, nn = idx - mm * NT;
    float dx = 0.f, ds = 0.f;
    #pragma unroll
    for (int z = 0; z < KSPLIT; ++z) {
        dx += g_PX[(size_t)z * BQ * NT + idx];
        ds += g_PS[(size_t)z * BQ * NT + idx];
    }
    const float invP = 1.f / (float)NP;
    float cost_mask = (g_sumSP[mm] - dx) * invP;
    float dice = 1.f - (2.f * ds + 1.f) / (g_sumS[mm] + g_sumT[nn] + 1.f);
    out[idx] = 2.f * g_CC[idx] + 5.f * cost_mask + 5.f * dice;
}

// ---------------- launch -----------------------------------------------------
extern "C" void kernel_launch(void* const* d_in, const int* in_sizes, int n_in,
                              void* d_out, int out_size) {
    const float* pred_logits = (const float*)d_in[0];   // (4,300,80)
    const float* pred_masks  = (const float*)d_in[1];   // (4,300,256,256)
    const int*   tgt_ids     = (const int*)  d_in[2];   // (200,)
    const float* tgt_masks   = (const float*)d_in[3];   // (200,256,256)
    const int*   point_idx   = (const int*)  d_in[4];   // (12544,)
    float* out = (float*)d_out;                         // (4,300,200)

    cudaFuncSetAttribute(gemm_kernel,
                         cudaFuncAttributeMaxDynamicSharedMemorySize, SMEM_BYTES);

    sort_kernel   <<<1, 1024>>>(point_idx);
    class_kernel  <<<BQ / 4, 128>>>(pred_logits, tgt_ids);
    gather_t_kernel<<<NT,     256>>>(tgt_masks);
    gather_x_kernel<<<BQ,     256>>>(pred_masks);
    dim3 grid((NT + BN - 1) / BN, (BQ + BM - 1) / BM, KSPLIT);  // (4, 38, 4)
    gemm_kernel<<<grid, 256, SMEM_BYTES>>>();
    combine_kernel<<<(BQ * NT + 255) / 256, 256>>>(out);
}

// round 9
// speedup vs baseline: 1.7329x; 1.7329x over previous
#include <cuda_runtime.h>
#include <cuda_bf16.h>
#include <cstdint>

// Problem constants (fixed by the dataset)
#define BQ    1200      // B*Q rows
#define NC    80        // classes
#define NT    200       // targets
#define HW    65536     // H*W
#define NP    12544     // sampled points (K of the GEMM)

// GEMM tiling
#define BM    32
#define BN    64
#define BK    64
#define KPAD  72        // smem row stride in bf16 (+8 avoids bank conflicts)
#define KIT   (NP / BK) // 196
#define KSPLIT 4
#define ITERS (KIT / KSPLIT)  // 49

#define AB_STAGE (BM * KPAD)          // 2304 elems per X/S stage
#define T_STAGE  (BN * KPAD)          // 4608 elems per T stage
#define SMEM_ELEMS (3 * (2 * AB_STAGE + T_STAGE))
#define SMEM_BYTES (SMEM_ELEMS * 2)   // 55296 bytes

// ---------------- scratch (static device allocations; no cudaMalloc) -------
__device__ __align__(256) __nv_bfloat16 g_X[(size_t)BQ * NP];   // x (bf16)
__device__ __align__(256) __nv_bfloat16 g_S[(size_t)BQ * NP];   // sigmoid(x)
__device__ __align__(256) __nv_bfloat16 g_T[(size_t)NT * NP];   // gathered targets
__device__ float g_CC[BQ * NT];    // class cost  (-prob[tgt_id])
__device__ float g_sumSP[BQ];      // sum softplus(x)  per row
__device__ float g_sumS[BQ];       // sum sigmoid(x)   per row
__device__ float g_sumT[NT];       // sum t            per target
__device__ int   g_sidx[NP];       // sorted point indices
__device__ float g_PX[(size_t)KSPLIT * BQ * NT];  // split-K partials of x@t'
__device__ float g_PS[(size_t)KSPLIT * BQ * NT];  // split-K partials of s@t'

// ---------------- helpers ---------------------------------------------------
__device__ __forceinline__ void cp16(void* smem, const void* gmem) {
    unsigned s = (unsigned)__cvta_generic_to_shared(smem);
    asm volatile("cp.async.cg.shared.global [%0], [%1], 16;\n" :: "r"(s), "l"(gmem));
}
__device__ __forceinline__ void cp_commit() {
    asm volatile("cp.async.commit_group;\n" ::: "memory");
}
__device__ __forceinline__ void cp_wait1() {
    asm volatile("cp.async.wait_group 1;\n" ::: "memory");
}
__device__ __forceinline__ void ldsm4(unsigned addr, unsigned& r0, unsigned& r1,
                                      unsigned& r2, unsigned& r3) {
    asm volatile("ldmatrix.sync.aligned.m8n8.x4.shared.b16 {%0,%1,%2,%3}, [%4];\n"
                 : "=r"(r0), "=r"(r1), "=r"(r2), "=r"(r3) : "r"(addr));
}
__device__ __forceinline__ void mma16816(float* d, const unsigned* a,
                                         unsigned b0, unsigned b1) {
    asm volatile(
        "mma.sync.aligned.m16n8k16.row.col.f32.bf16.bf16.f32 "
        "{%0,%1,%2,%3},{%4,%5,%6,%7},{%8,%9},{%0,%1,%2,%3};\n"
        : "+f"(d[0]), "+f"(d[1]), "+f"(d[2]), "+f"(d[3])
        : "r"(a[0]), "r"(a[1]), "r"(a[2]), "r"(a[3]), "r"(b0), "r"(b1));
}

__device__ __forceinline__ float block_reduce_sum(float v, float* sbuf) {
    #pragma unroll
    for (int o = 16; o > 0; o >>= 1) v += __shfl_xor_sync(0xFFFFFFFFu, v, o);
    int w = threadIdx.x >> 5;
    if ((threadIdx.x & 31) == 0) sbuf[w] = v;
    __syncthreads();
    float r = 0.f;
    if (threadIdx.x < 8) {
        r = sbuf[threadIdx.x];
        #pragma unroll
        for (int o = 4; o > 0; o >>= 1) r += __shfl_xor_sync(0xFFu, r, o);
    }
    return r;  // valid in thread 0
}

// ---------------- kernel 0: sort point indices (bitmask counting sort) ------
// 1 block x 1024 threads. Indices are 12544 distinct values in [0, 65536).
__global__ void sort_kernel(const int* __restrict__ point_idx) {
    __shared__ unsigned mask[2048];   // 65536 bits
    __shared__ int psum[1024];
    int tid = threadIdx.x;
    mask[tid] = 0u; mask[tid + 1024] = 0u;
    __syncthreads();
    for (int p = tid; p < NP; p += 1024) {
        int v = point_idx[p];
        atomicOr(&mask[v >> 5], 1u << (v & 31));
    }
    __syncthreads();
    unsigned m0 = mask[2 * tid], m1 = mask[2 * tid + 1];
    int c0 = __popc(m0);
    int s = c0 + __popc(m1);
    psum[tid] = s;
    __syncthreads();
    // Hillis-Steele inclusive scan over 1024 entries
    #pragma unroll
    for (int off = 1; off < 1024; off <<= 1) {
        int v = (tid >= off) ? psum[tid - off] : 0;
        __syncthreads();
        psum[tid] += v;
        __syncthreads();
    }
    int o = psum[tid] - s;   // exclusive prefix
    int base0 = (2 * tid) << 5, base1 = (2 * tid + 1) << 5;
    while (m0) { int b = __ffs(m0) - 1; m0 &= m0 - 1; g_sidx[o++] = base0 + b; }
    o = psum[tid] - s + c0;
    while (m1) { int b = __ffs(m1) - 1; m1 &= m1 - 1; g_sidx[o++] = base1 + b; }
}

// ---------------- kernel 1: class cost --------------------------------------
__global__ void class_kernel(const float* __restrict__ logits,
                             const int* __restrict__ tgt_ids) {
    __shared__ float probs[4][NC];
    __shared__ int s_ids[NT];
    int warp = threadIdx.x >> 5, lane = threadIdx.x & 31;
    for (int i = threadIdx.x; i < NT; i += 128) s_ids[i] = tgt_ids[i];
    __syncthreads();

    int r = blockIdx.x * 4 + warp;
    const float* L = logits + (size_t)r * NC;
    float v[3];
    float mx = -1e30f;
    #pragma unroll
    for (int j = 0; j < 3; j++) {
        int c = lane + 32 * j;
        v[j] = (c < NC) ? L[c] : -1e30f;
        mx = fmaxf(mx, v[j]);
    }
    #pragma unroll
    for (int o = 16; o > 0; o >>= 1) mx = fmaxf(mx, __shfl_xor_sync(~0u, mx, o));
    float e[3], se = 0.f;
    #pragma unroll
    for (int j = 0; j < 3; j++) {
        int c = lane + 32 * j;
        e[j] = (c < NC) ? expf(v[j] - mx) : 0.f;
        se += e[j];
    }
    #pragma unroll
    for (int o = 16; o > 0; o >>= 1) se += __shfl_xor_sync(~0u, se, o);
    float inv = 1.f / se;
    #pragma unroll
    for (int j = 0; j < 3; j++) {
        int c = lane + 32 * j;
        if (c < NC) probs[warp][c] = e[j] * inv;
    }
    __syncwarp();
    for (int n = lane; n < NT; n += 32)
        g_CC[r * NT + n] = -probs[warp][s_ids[n]];
}

// ---------------- kernel 2: gather targets (sorted order) -------------------
__global__ void gather_t_kernel(const float* __restrict__ tgt_masks) {
    __shared__ float sbuf[8];
    int n = blockIdx.x;
    const float* row = tgt_masks + (size_t)n * HW;
    float st = 0.f;
    for (int p = threadIdx.x; p < NP; p += 256) {
        float t = __ldg(row + __ldg(g_sidx + p));
        g_T[(size_t)n * NP + p] = __float2bfloat16(t);
        st += t;
    }
    float tot = block_reduce_sum(st, sbuf);
    if (threadIdx.x == 0) g_sumT[n] = tot;
}

// ---------------- kernel 3: gather + transform predictions (sorted, fast math)
__global__ void gather_x_kernel(const float* __restrict__ pred_masks) {
    __shared__ float sbuf[8];
    int m = blockIdx.x;
    const float* row = pred_masks + (size_t)m * HW;
    float sSP = 0.f, sS = 0.f;
    for (int p = threadIdx.x; p < NP; p += 256) {
        float x = __ldg(row + __ldg(g_sidx + p));
        float e   = __expf(-fabsf(x));            // e^{-|x|}
        float inv = __frcp_rn(1.f + e);           // 1/(1+e)
        float sg  = (x >= 0.f) ? inv : e * inv;   // sigmoid(x)
        float sp  = fmaxf(x, 0.f) + __logf(1.f + e);  // softplus(x)
        g_X[(size_t)m * NP + p] = __float2bfloat16(x);
        g_S[(size_t)m * NP + p] = __float2bfloat16(sg);
        sSP += sp; sS += sg;
    }
    float t1 = block_reduce_sum(sSP, sbuf);
    if (threadIdx.x == 0) g_sumSP[m] = t1;
    __syncthreads();
    float t2 = block_reduce_sum(sS, sbuf);
    if (threadIdx.x == 0) g_sumS[m] = t2;
}

// ---------------- kernel 4: dual GEMM, split-K, 3-stage pipeline -------------
// grid (4, 38, KSPLIT) x 256 threads (8 warps: 2(M) x 4(N))
__global__ void __launch_bounds__(256)
gemm_kernel() {
    extern __shared__ __nv_bfloat16 smem[];
    __nv_bfloat16* sX = smem;                    // [3][BM][KPAD]
    __nv_bfloat16* sS = smem + 3 * AB_STAGE;     // [3][BM][KPAD]
    __nv_bfloat16* sT = smem + 6 * AB_STAGE;     // [3][BN][KPAD]

    const int tid  = threadIdx.x;
    const int m0   = blockIdx.y * BM;
    const int n0   = blockIdx.x * BN;
    const int kbase = blockIdx.z * ITERS * BK;

    // producer mapping
    const int pr  = tid >> 3;             // 0..31
    const int pc  = (tid & 7) * 8;        // element col of the 16B vector
    const size_t gxm = (size_t)min(m0 + pr, BQ - 1) * NP;
    const size_t gt0 = (size_t)min(n0 + pr, NT - 1) * NP;
    const size_t gt1 = (size_t)min(n0 + pr + 32, NT - 1) * NP;

    // consumer mapping
    const int warp = tid >> 5, lane = tid & 31;
    const int wm = (warp >> 2) * 16;      // 0 or 16
    const int wn = (warp & 3) * 16;       // 0,16,32,48
    const int lrow = lane & 15;
    const int lcol = (lane >> 4) * 8;

    const unsigned baseX = (unsigned)__cvta_generic_to_shared(sX);
    const unsigned baseS = (unsigned)__cvta_generic_to_shared(sS);
    const unsigned baseT = (unsigned)__cvta_generic_to_shared(sT);
    const unsigned offA  = (unsigned)(((wm + lrow) * KPAD + lcol) * 2);
    const unsigned offB  = (unsigned)(((wn + lrow) * KPAD + lcol) * 2);
    const unsigned stgAB = (unsigned)(AB_STAGE * 2);
    const unsigned stgT  = (unsigned)(T_STAGE * 2);

    float accX[2][4] = {}, accS[2][4] = {};

    auto issue = [&](int st, int buf) {
        const int k0 = kbase + st * BK;
        cp16(sX + buf * AB_STAGE + pr * KPAD + pc,        g_X + gxm + k0 + pc);
        cp16(sS + buf * AB_STAGE + pr * KPAD + pc,        g_S + gxm + k0 + pc);
        cp16(sT + buf * T_STAGE + pr * KPAD + pc,         g_T + gt0 + k0 + pc);
        cp16(sT + buf * T_STAGE + (pr + 32) * KPAD + pc,  g_T + gt1 + k0 + pc);
    };

    // prologue: stages 0,1
    issue(0, 0); cp_commit();
    issue(1, 1); cp_commit();

    #pragma unroll 1
    for (int it = 0; it < ITERS; ++it) {
        cp_wait1();
        __syncthreads();

        const int buf = it % 3;
        const unsigned aX = baseX + buf * stgAB + offA;
        const unsigned aS = baseS + buf * stgAB + offA;
        const unsigned aT = baseT + buf * stgT  + offB;
        #pragma unroll
        for (int kk = 0; kk < 4; ++kk) {
            unsigned xf[4], sf[4], tf[4];
            ldsm4(aX + kk * 32, xf[0], xf[1], xf[2], xf[3]);
            ldsm4(aS + kk * 32, sf[0], sf[1], sf[2], sf[3]);
            ldsm4(aT + kk * 32, tf[0], tf[1], tf[2], tf[3]);
            mma16816(accX[0], xf, tf[0], tf[2]);
            mma16816(accX[1], xf, tf[1], tf[3]);
            mma16816(accS[0], sf, tf[0], tf[2]);
            mma16816(accS[1], sf, tf[1], tf[3]);
        }

        // prefetch stage it+2 into the buffer consumed at iter it-1.
        const int st = it + 2;
        if (st < ITERS) issue(st, st % 3);
        cp_commit();   // always commit to keep group count aligned
    }

    // write split-K partials
    const int groupId = lane >> 2, tig = lane & 3;
    float* px = g_PX + (size_t)blockIdx.z * BQ * NT;
    float* ps = g_PS + (size_t)blockIdx.z * BQ * NT;
    #pragma unroll
    for (int nsub = 0; nsub < 2; ++nsub) {
        #pragma unroll
        for (int e2 = 0; e2 < 4; ++e2) {
            int mm = m0 + wm + groupId + ((e2 >= 2) ? 8 : 0);
            int nn = n0 + wn + nsub * 8 + 2 * tig + (e2 & 1);
            if (mm < BQ && nn < NT) {
                px[mm * NT + nn] = accX[nsub][e2];
                ps[mm * NT + nn] = accS[nsub][e2];
            }
        }
    }
}

// ---------------- kernel 5: combine partials + epilogue ----------------------
__global__ void combine_kernel(float* __restrict__ out) {
    int idx = blockIdx.x * 256 + threadIdx.x;
    if (idx >= BQ * NT) return;
    int mm = idx / NT, nn = idx - mm * NT;
    float dx = 0.f, ds = 0.f;
    #pragma unroll
    for (int z = 0; z < KSPLIT; ++z) {
        dx += g_PX[(size_t)z * BQ * NT + idx];
        ds += g_PS[(size_t)z * BQ * NT + idx];
    }
    const float invP = 1.f / (float)NP;
    float cost_mask = (g_sumSP[mm] - dx) * invP;
    float dice = 1.f - (2.f * ds + 1.f) / (g_sumS[mm] + g_sumT[nn] + 1.f);
    out[idx] = 2.f * g_CC[idx] + 5.f * cost_mask + 5.f * dice;
}

// ---------------- launch -----------------------------------------------------
extern "C" void kernel_launch(void* const* d_in, const int* in_sizes, int n_in,
                              void* d_out, int out_size) {
    const float* pred_logits = (const float*)d_in[0];   // (4,300,80)
    const float* pred_masks  = (const float*)d_in[1];   // (4,300,256,256)
    const int*   tgt_ids     = (const int*)  d_in[2];   // (200,)
    const float* tgt_masks   = (const float*)d_in[3];   // (200,256,256)
    const int*   point_idx   = (const int*)  d_in[4];   // (12544,)
    float* out = (float*)d_out;                         // (4,300,200)

    cudaFuncSetAttribute(gemm_kernel,
                         cudaFuncAttributeMaxDynamicSharedMemorySize, SMEM_BYTES);

    sort_kernel   <<<1, 1024>>>(point_idx);
    class_kernel  <<<BQ / 4, 128>>>(pred_logits, tgt_ids);
    gather_t_kernel<<<NT,     256>>>(tgt_masks);
    gather_x_kernel<<<BQ,     256>>>(pred_masks);
    dim3 grid((NT + BN - 1) / BN, (BQ + BM - 1) / BM, KSPLIT);  // (4, 38, 4)
    gemm_kernel<<<grid, 256, SMEM_BYTES>>>();
    combine_kernel<<<(BQ * NT + 255) / 256, 256>>>(out);
}